// round 2
// baseline (speedup 1.0000x reference)
#include <cuda_runtime.h>
#include <math.h>

// ---------------- problem constants ----------------
#define BB   16      // batch (trees)
#define TT   32      // nodes per tree
#define LL   64      // token positions
#define DM   768     // d_model
#define HH   12      // heads
#define HD   64      // head dim
#define FF   2048    // ffn dim
#define ZZ   100     // d_z
#define NMAX 496     // max packed responses = 16*31

enum { OP_NONE = 0, OP_RELU = 1, OP_TANH = 2 };

// ---------------- device scratch (static, no allocation) ----------------
__device__ float g_X  [NMAX * LL * DM];          // activations
__device__ float g_QKV[NMAX * LL * 3 * DM];
__device__ float g_ATT[NMAX * LL * DM];
__device__ float g_Y  [NMAX * LL * DM];
__device__ float g_HID[NMAX * LL * FF];
__device__ float g_Z  [NMAX * LL * ZZ];
__device__ float g_S  [768 * NMAX * NMAX];       // [l*12+h][n][m] attention scores
__device__ float g_MSK[NMAX * LL];               // gathered attention_mask rows
__device__ float g_meanE[NMAX * DM];             // mean over L of gathered emb
__device__ float g_s  [NMAX];                    // anomaly scores
__device__ int   g_Ntot;
__device__ int   g_nresp[BB];
__device__ int   g_next [BB];
__device__ int   g_bidx [NMAX];
__device__ int   g_tidx [NMAX];
__device__ int   g_nodefull[BB * TT];
__device__ int   g_oh      [BB * TT];

// ---------------- setup: ragged packing metadata (device-side!) ----------------
__global__ void setup_kernel(const int* __restrict__ tree_lens) {
    if (threadIdx.x == 0 && blockIdx.x == 0) {
        int tot = 0;
        for (int b = 0; b < BB; b++) {
            int tl = tree_lens[b];
            int nr = tl - 1;
            g_nresp[b] = nr;
            int ne = (int)floor((double)nr * 0.05);
            if (ne < 1) ne = 1;
            g_next[b] = ne;
            for (int j = 1; j < tl; j++) {
                g_bidx[tot] = b;
                g_tidx[tot] = j;
                tot++;
            }
        }
        g_Ntot = tot;
    }
}

// ---------------- gather reply rows + mask ----------------
__global__ void gather_kernel(const float* __restrict__ emb,
                              const float* __restrict__ amask) {
    int n = blockIdx.x;
    int l = blockIdx.y;
    if (n >= g_Ntot) return;
    int bi = g_bidx[n], ti = g_tidx[n];
    const float* src = emb + (((size_t)bi * TT + ti) * LL + l) * DM;
    float* dst = g_X + ((size_t)n * LL + l) * DM;
    for (int d = threadIdx.x; d < DM; d += blockDim.x) dst[d] = src[d];
    if (threadIdx.x == 0)
        g_MSK[n * LL + l] = amask[((size_t)bi * TT + ti) * LL + l];
}

// mean over L of gathered emb (needed at the end)
__global__ void meanE_kernel() {
    int n = blockIdx.x;
    if (n >= g_Ntot) return;
    int d = blockIdx.y * 256 + threadIdx.x;
    float s = 0.f;
    for (int l = 0; l < LL; l++) s += g_X[((size_t)n * LL + l) * DM + d];
    g_meanE[n * DM + d] = s * (1.f / (float)LL);
}

// ---------------- generic NT GEMM: C[M,N] = A[M,K] * W[N,K]^T + bias ----------------
// BM=128, BN=64, BK=16, 256 threads, 8x4 per-thread microtile. M = g_Ntot*64 (dynamic).
template <int OP>
__global__ void __launch_bounds__(256)
gemm_nt(const float* __restrict__ A, const float* __restrict__ W,
        const float* __restrict__ bias, float* __restrict__ C,
        int N, int K) {
    const int BM = 128, BN = 64, BK = 16;
    int M = g_Ntot * LL;
    int m0 = blockIdx.y * BM;
    if (m0 >= M) return;
    int n0 = blockIdx.x * BN;

    __shared__ __align__(16) float As[BK][BM];
    __shared__ __align__(16) float Bs[BK][BN];

    int tid = threadIdx.x;
    int tx = tid & 15;          // 0..15 -> n
    int ty = tid >> 4;          // 0..15 -> m
    int lr = tid >> 2;          // 0..63
    int lc = (tid & 3) * 4;     // 0,4,8,12

    float acc[8][4];
#pragma unroll
    for (int i = 0; i < 8; i++)
#pragma unroll
        for (int j = 0; j < 4; j++) acc[i][j] = 0.f;

    for (int k0 = 0; k0 < K; k0 += BK) {
        // load A tile (transposed into smem)
#pragma unroll
        for (int p = 0; p < 2; p++) {
            int m = m0 + lr + p * 64;
            const float* arow = A + (size_t)m * K + k0 + lc;
            bool mok = (m < M);
#pragma unroll
            for (int j = 0; j < 4; j++) {
                int k = k0 + lc + j;
                As[lc + j][lr + p * 64] = (mok && k < K) ? arow[j] : 0.f;
            }
        }
        // load W tile
        {
            int n = n0 + lr;
            const float* wrow = W + (size_t)n * K + k0 + lc;
            bool nok = (n < N);
#pragma unroll
            for (int j = 0; j < 4; j++) {
                int k = k0 + lc + j;
                Bs[lc + j][lr] = (nok && k < K) ? wrow[j] : 0.f;
            }
        }
        __syncthreads();
#pragma unroll
        for (int kk = 0; kk < BK; kk++) {
            float4 a0 = *reinterpret_cast<const float4*>(&As[kk][ty * 8]);
            float4 a1 = *reinterpret_cast<const float4*>(&As[kk][ty * 8 + 4]);
            float4 bv = *reinterpret_cast<const float4*>(&Bs[kk][tx * 4]);
            float a[8] = {a0.x, a0.y, a0.z, a0.w, a1.x, a1.y, a1.z, a1.w};
            float b[4] = {bv.x, bv.y, bv.z, bv.w};
#pragma unroll
            for (int i = 0; i < 8; i++)
#pragma unroll
                for (int j = 0; j < 4; j++) acc[i][j] = fmaf(a[i], b[j], acc[i][j]);
        }
        __syncthreads();
    }
#pragma unroll
    for (int i = 0; i < 8; i++) {
        int m = m0 + ty * 8 + i;
        if (m >= M) continue;
#pragma unroll
        for (int j = 0; j < 4; j++) {
            int n = n0 + tx * 4 + j;
            if (n >= N) continue;
            float v = acc[i][j] + bias[n];
            if (OP == OP_RELU) v = fmaxf(v, 0.f);
            if (OP == OP_TANH) v = tanhf(v);
            C[(size_t)m * N + n] = v;
        }
    }
}

// ---------------- attention scores: S[lh,n,m] = 0.125*q.k + mask[m,l] ----------------
__global__ void __launch_bounds__(256) scores_kernel() {
    int Nt = g_Ntot;
    int n0 = blockIdx.x * 64;
    int m0 = blockIdx.y * 64;
    if (n0 >= Nt || m0 >= Nt) return;
    int lh = blockIdx.z;
    int l = lh / HH, h = lh % HH;

    __shared__ float Qs[64][65];
    __shared__ float Ks[64][65];

    int tid = threadIdx.x;
    int r = tid >> 2;            // 0..63
    int c0 = (tid & 3) * 16;     // 0,16,32,48
    {
        int n = n0 + r;
        const float* srcq = g_QKV + ((size_t)n * LL + l) * (3 * DM) + h * HD;
        int m = m0 + r;
        const float* srck = g_QKV + ((size_t)m * LL + l) * (3 * DM) + DM + h * HD;
#pragma unroll
        for (int j = 0; j < 16; j++) Qs[r][c0 + j] = (n < Nt) ? srcq[c0 + j] : 0.f;
#pragma unroll
        for (int j = 0; j < 16; j++) Ks[r][c0 + j] = (m < Nt) ? srck[c0 + j] : 0.f;
    }
    __syncthreads();

    int tx = tid & 15, ty = tid >> 4;
    float acc[4][4];
#pragma unroll
    for (int i = 0; i < 4; i++)
#pragma unroll
        for (int j = 0; j < 4; j++) acc[i][j] = 0.f;

#pragma unroll 8
    for (int k = 0; k < 64; k++) {
        float a[4], b[4];
#pragma unroll
        for (int i = 0; i < 4; i++) a[i] = Qs[ty * 4 + i][k];
#pragma unroll
        for (int j = 0; j < 4; j++) b[j] = Ks[tx * 4 + j][k];
#pragma unroll
        for (int i = 0; i < 4; i++)
#pragma unroll
            for (int j = 0; j < 4; j++) acc[i][j] = fmaf(a[i], b[j], acc[i][j]);
    }
#pragma unroll
    for (int i = 0; i < 4; i++) {
        int n = n0 + ty * 4 + i;
        if (n >= Nt) continue;
        float* srow = g_S + ((size_t)lh * NMAX + n) * NMAX;
#pragma unroll
        for (int j = 0; j < 4; j++) {
            int m = m0 + tx * 4 + j;
            if (m >= Nt) continue;
            srow[m] = acc[i][j] * 0.125f + g_MSK[m * LL + l];
        }
    }
}

// ---------------- row softmax over m ----------------
__global__ void softmax_kernel() {
    int n = blockIdx.x;
    int lh = blockIdx.y;
    int Nt = g_Ntot;
    if (n >= Nt) return;
    float* row = g_S + ((size_t)lh * NMAX + n) * NMAX;
    int t = threadIdx.x;  // 128
    __shared__ float red[128];

    float mx = -INFINITY;
    for (int j = t; j < Nt; j += 128) mx = fmaxf(mx, row[j]);
    red[t] = mx; __syncthreads();
    for (int s = 64; s > 0; s >>= 1) { if (t < s) red[t] = fmaxf(red[t], red[t + s]); __syncthreads(); }
    mx = red[0]; __syncthreads();

    float sum = 0.f;
    for (int j = t; j < Nt; j += 128) { float e = __expf(row[j] - mx); row[j] = e; sum += e; }
    red[t] = sum; __syncthreads();
    for (int s = 64; s > 0; s >>= 1) { if (t < s) red[t] += red[t + s]; __syncthreads(); }
    float inv = 1.f / red[0];
    for (int j = t; j < Nt; j += 128) row[j] *= inv;
}

// ---------------- O = P @ V ----------------
__global__ void __launch_bounds__(256) pv_kernel() {
    int Nt = g_Ntot;
    int n0 = blockIdx.x * 64;
    if (n0 >= Nt) return;
    int lh = blockIdx.y;
    int l = lh / HH, h = lh % HH;

    __shared__ float Ps[64][65];
    __shared__ float Vs[64][65];

    int tid = threadIdx.x;
    int r = tid >> 2;
    int c0 = (tid & 3) * 16;
    int tx = tid & 15, ty = tid >> 4;

    float acc[4][4];
#pragma unroll
    for (int i = 0; i < 4; i++)
#pragma unroll
        for (int j = 0; j < 4; j++) acc[i][j] = 0.f;

    for (int m0 = 0; m0 < Nt; m0 += 64) {
        {
            int n = n0 + r;
            const float* prow = g_S + ((size_t)lh * NMAX + n) * NMAX;
#pragma unroll
            for (int j = 0; j < 16; j++) {
                int m = m0 + c0 + j;
                Ps[r][c0 + j] = (n < Nt && m < Nt) ? prow[m] : 0.f;
            }
            int mr = m0 + r;
            const float* vsrc = g_QKV + ((size_t)mr * LL + l) * (3 * DM) + 2 * DM + h * HD;
#pragma unroll
            for (int j = 0; j < 16; j++) Vs[r][c0 + j] = (mr < Nt) ? vsrc[c0 + j] : 0.f;
        }
        __syncthreads();
#pragma unroll 8
        for (int k = 0; k < 64; k++) {
            float a[4], b[4];
#pragma unroll
            for (int i = 0; i < 4; i++) a[i] = Ps[ty * 4 + i][k];
#pragma unroll
            for (int j = 0; j < 4; j++) b[j] = Vs[k][tx * 4 + j];
#pragma unroll
            for (int i = 0; i < 4; i++)
#pragma unroll
                for (int j = 0; j < 4; j++) acc[i][j] = fmaf(a[i], b[j], acc[i][j]);
        }
        __syncthreads();
    }
#pragma unroll
    for (int i = 0; i < 4; i++) {
        int n = n0 + ty * 4 + i;
        if (n >= Nt) continue;
#pragma unroll
        for (int j = 0; j < 4; j++) {
            int d = tx * 4 + j;
            g_ATT[((size_t)n * LL + l) * DM + h * HD + d] = acc[i][j];
        }
    }
}

// ---------------- residual + LayerNorm (in place on X) ----------------
__global__ void add_ln_kernel(float* __restrict__ X, const float* __restrict__ Yv,
                              const float* __restrict__ g, const float* __restrict__ b) {
    int row = blockIdx.x;
    if (row >= g_Ntot * LL) return;
    float* x = X + (size_t)row * DM;
    const float* y = Yv + (size_t)row * DM;
    int t = threadIdx.x;  // 256
    float v[3], s = 0.f, s2 = 0.f;
#pragma unroll
    for (int i = 0; i < 3; i++) {
        float u = x[t + 256 * i] + y[t + 256 * i];
        v[i] = u; s += u; s2 += u * u;
    }
    __shared__ float rs[256], rs2[256];
    rs[t] = s; rs2[t] = s2; __syncthreads();
    for (int st = 128; st > 0; st >>= 1) {
        if (t < st) { rs[t] += rs[t + st]; rs2[t] += rs2[t + st]; }
        __syncthreads();
    }
    float mean = rs[0] * (1.f / (float)DM);
    float var = rs2[0] * (1.f / (float)DM) - mean * mean;
    float inv = rsqrtf(var + 1e-5f);
#pragma unroll
    for (int i = 0; i < 3; i++) {
        int d = t + 256 * i;
        x[d] = (v[i] - mean) * inv * g[d] + b[d];
    }
}

// ---------------- anomaly score per response ----------------
__global__ void anomaly_kernel() {
    int n = blockIdx.x;
    if (n >= g_Ntot) return;
    int t = threadIdx.x;  // 256
    float acc = 0.f;
#pragma unroll
    for (int i = 0; i < 3; i++) {
        int d = t + 256 * i;
        float m = 0.f;
        for (int l = 0; l < LL; l++) m += g_X[((size_t)n * LL + l) * DM + d];
        m *= (1.f / (float)LL);
        float diff = m - g_meanE[n * DM + d];
        acc += diff * diff;
    }
    __shared__ float red[256];
    red[t] = acc; __syncthreads();
    for (int s = 128; s > 0; s >>= 1) { if (t < s) red[t] += red[t + s]; __syncthreads(); }
    if (t == 0) g_s[n] = red[0];
}

// ---------------- per-tree stable top-k selection ----------------
__global__ void select_kernel() {
    int b = threadIdx.x;
    if (b >= BB) return;
    int nr = g_nresp[b];
    int ne = g_next[b];
    bool used[TT];
    int ohf[TT];
#pragma unroll
    for (int j = 0; j < TT; j++) { used[j] = false; ohf[j] = 0; }
    ohf[0] = 1;
    g_nodefull[b * TT + 0] = 0;
    for (int i = 0; i < TT - 1; i++) {
        int node = 0;
        if (i < ne) {
            float best = INFINITY; int bj = 0;
            for (int j = 0; j < nr; j++) {
                if (!used[j] && g_s[j] < best) { best = g_s[j]; bj = j; }
            }
            used[bj] = true;
            node = bj + 1;
            ohf[node] = 1;
        }
        g_nodefull[b * TT + i + 1] = node;
    }
    for (int t = 0; t < TT; t++) g_oh[b * TT + t] = ohf[t];
}

// ---------------- output writers ----------------
__global__ void out_small_kernel(float* __restrict__ out, long long off_oh,
                                 long long off_sc, long long off_tl, int has_sc) {
    int t = blockIdx.x * blockDim.x + threadIdx.x;
    if (t < BB * TT) out[off_oh + t] = (float)g_oh[t];
    else if (t < BB * TT + BB) out[off_tl + (t - BB * TT)] = (float)(1 + g_next[t - BB * TT]);
    else if (t == BB * TT + BB && has_sc) out[off_sc] = 0.f;
}

__global__ void ext_mask_kernel(float* __restrict__ out, long long off) {
    int bt = blockIdx.x;
    out[off + (size_t)bt * LL + threadIdx.x] = (float)g_oh[bt];
}

__global__ void new_msk_kernel(const float* __restrict__ amask,
                               float* __restrict__ out, long long off) {
    int bt = blockIdx.x;
    int b = bt >> 5, t = bt & 31;
    int node = g_nodefull[bt];
    float valid = (t == 0 || (t - 1) < g_next[b]) ? 1.f : 0.f;
    out[off + (size_t)bt * LL + threadIdx.x] =
        amask[((size_t)b * TT + node) * LL + threadIdx.x] * valid;
}

__global__ void new_emb_kernel(const float* __restrict__ emb,
                               float* __restrict__ out, long long off) {
    // 49152 floats per (b,t) slot; 192 blocks of 256 threads per slot
    int bt = blockIdx.x / 192;
    int r = (blockIdx.x % 192) * 256 + threadIdx.x;
    int b = bt >> 5;
    int node = g_nodefull[bt];
    out[off + (size_t)bt * (LL * DM) + r] =
        emb[((size_t)b * TT + node) * (LL * DM) + r];
}

// ---------------- host orchestration ----------------
static void run_layer(float* X, float* QKV, float* ATT, float* Y, float* HID,
                      const float* qkvw, const float* qkvb,
                      const float* outw, const float* outb,
                      const float* g1, const float* b1,
                      const float* w1, const float* c1,
                      const float* w2, const float* c2,
                      const float* g2, const float* b2) {
    const int GY = (NMAX * LL + 127) / 128;  // 248
    gemm_nt<OP_NONE><<<dim3(36, GY), 256>>>(X, qkvw, qkvb, QKV, 3 * DM, DM);
    scores_kernel<<<dim3(8, 8, LL * HH), 256>>>();
    softmax_kernel<<<dim3(NMAX, LL * HH), 128>>>();
    pv_kernel<<<dim3(8, LL * HH), 256>>>();
    gemm_nt<OP_NONE><<<dim3(12, GY), 256>>>(ATT, outw, outb, Y, DM, DM);
    add_ln_kernel<<<NMAX * LL, 256>>>(X, Y, g1, b1);
    gemm_nt<OP_RELU><<<dim3(32, GY), 256>>>(X, w1, c1, HID, FF, DM);
    gemm_nt<OP_NONE><<<dim3(12, GY), 256>>>(HID, w2, c2, Y, DM, FF);
    add_ln_kernel<<<NMAX * LL, 256>>>(X, Y, g2, b2);
}

extern "C" void kernel_launch(void* const* d_in, const int* in_sizes, int n_in,
                              void* d_out, int out_size) {
    const int*   tree_lens = (const int*)d_in[0];
    const float* emb       = (const float*)d_in[1];
    const float* amask     = (const float*)d_in[2];
    const float* P[28];
    for (int i = 3; i < 31; i++) P[i - 3] = (const float*)d_in[i];
    float* out = (float*)d_out;

    // scratch addresses
    float *pX, *pQKV, *pATT, *pY, *pHID, *pZ;
    cudaGetSymbolAddress((void**)&pX, g_X);
    cudaGetSymbolAddress((void**)&pQKV, g_QKV);
    cudaGetSymbolAddress((void**)&pATT, g_ATT);
    cudaGetSymbolAddress((void**)&pY, g_Y);
    cudaGetSymbolAddress((void**)&pHID, g_HID);
    cudaGetSymbolAddress((void**)&pZ, g_Z);

    // output layout (handle presence/absence of the python-int scalar slot)
    const long long NE_ELEMS = (long long)BB * TT * LL * DM;           // 25165824
    const long long TOT_W = 512 + 32768 + 1 + 16 + NE_ELEMS + 32768;   // 25231889
    int has_sc = ((long long)out_size == TOT_W - 1) ? 0 : 1;
    long long off_oh = 0;
    long long off_em = 512;
    long long off_sc = 512 + 32768;
    long long off_tl = off_sc + (has_sc ? 1 : 0);
    long long off_ne = off_tl + 16;
    long long off_nm = off_ne + NE_ELEMS;

    setup_kernel<<<1, 32>>>(tree_lens);
    gather_kernel<<<dim3(NMAX, LL), 256>>>(emb, amask);
    meanE_kernel<<<dim3(NMAX, 3), 256>>>();

    // encoder (2 layers): params 0..11
    for (int i = 0; i < 2; i++) {
        run_layer(pX, pQKV, pATT, pY, pHID,
                  P[0] + (size_t)i * 3 * DM * DM, P[1] + (size_t)i * 3 * DM,
                  P[2] + (size_t)i * DM * DM,     P[3] + (size_t)i * DM,
                  P[4] + (size_t)i * DM,          P[5] + (size_t)i * DM,
                  P[6] + (size_t)i * FF * DM,     P[7] + (size_t)i * FF,
                  P[8] + (size_t)i * DM * FF,     P[9] + (size_t)i * DM,
                  P[10] + (size_t)i * DM,         P[11] + (size_t)i * DM);
    }

    // projections: z = tanh(h @ pe_w^T + pe_b); zd = tanh(z @ pd_w^T + pd_b)
    const int GY = (NMAX * LL + 127) / 128;
    gemm_nt<OP_TANH><<<dim3(2, GY), 256>>>(pX, P[24], P[25], pZ, ZZ, DM);
    gemm_nt<OP_TANH><<<dim3(12, GY), 256>>>(pZ, P[26], P[27], pX, DM, ZZ);

    // decoder (2 layers): params 12..23
    for (int i = 0; i < 2; i++) {
        run_layer(pX, pQKV, pATT, pY, pHID,
                  P[12] + (size_t)i * 3 * DM * DM, P[13] + (size_t)i * 3 * DM,
                  P[14] + (size_t)i * DM * DM,     P[15] + (size_t)i * DM,
                  P[16] + (size_t)i * DM,          P[17] + (size_t)i * DM,
                  P[18] + (size_t)i * FF * DM,     P[19] + (size_t)i * FF,
                  P[20] + (size_t)i * DM * FF,     P[21] + (size_t)i * DM,
                  P[22] + (size_t)i * DM,          P[23] + (size_t)i * DM);
    }

    anomaly_kernel<<<NMAX, 256>>>();
    select_kernel<<<1, 32>>>();

    out_small_kernel<<<3, 256>>>(out, off_oh, off_sc, off_tl, has_sc);
    ext_mask_kernel<<<BB * TT, LL>>>(out, off_em);
    new_msk_kernel<<<BB * TT, LL>>>(amask, out, off_nm);
    new_emb_kernel<<<BB * TT * 192, 256>>>(emb, out, off_ne);
}

// round 4
// speedup vs baseline: 8.4292x; 8.4292x over previous
#include <cuda_runtime.h>
#include <cuda_bf16.h>
#include <math.h>
#include <stdint.h>

#define BB   16
#define TT   32
#define LL   64
#define DM   768
#define HH   12
#define HD   64
#define FF   2048
#define ZZ   100
#define NMAX 496
#define MROWS (NMAX * LL)

// ---------------- helpers ----------------
__device__ __forceinline__ uint32_t smem_u32(const void* p) {
    uint32_t a;
    asm("{ .reg .u64 t; cvta.to.shared.u64 t, %1; cvt.u32.u64 %0, t; }" : "=r"(a) : "l"(p));
    return a;
}
__device__ __forceinline__ void cp16(uint32_t dst, const void* src) {
    asm volatile("cp.async.cg.shared.global [%0], [%1], 16;" :: "r"(dst), "l"(src));
}
__device__ __forceinline__ void cp_commit() { asm volatile("cp.async.commit_group;" ::: "memory"); }
__device__ __forceinline__ void cp_wait0()  { asm volatile("cp.async.wait_group 0;" ::: "memory"); }
__device__ __forceinline__ void cp_wait1()  { asm volatile("cp.async.wait_group 1;" ::: "memory"); }
__device__ __forceinline__ void ldmx4(uint32_t& r0, uint32_t& r1, uint32_t& r2, uint32_t& r3,
                                      uint32_t addr) {
    asm volatile("ldmatrix.sync.aligned.m8n8.x4.shared.b16 {%0,%1,%2,%3}, [%4];"
                 : "=r"(r0), "=r"(r1), "=r"(r2), "=r"(r3) : "r"(addr));
}
__device__ __forceinline__ void mma16816(float* c, const uint32_t* a, const uint32_t* b) {
    asm volatile("mma.sync.aligned.m16n8k16.row.col.f32.bf16.bf16.f32 "
                 "{%0,%1,%2,%3}, {%4,%5,%6,%7}, {%8,%9}, {%0,%1,%2,%3};"
                 : "+f"(c[0]), "+f"(c[1]), "+f"(c[2]), "+f"(c[3])
                 : "r"(a[0]), "r"(a[1]), "r"(a[2]), "r"(a[3]), "r"(b[0]), "r"(b[1]));
}
__device__ __forceinline__ int imin(int a, int b) { return a < b ? a : b; }

// ---------------- device scratch ----------------
__device__ __nv_bfloat16 g_Xbf  [MROWS * DM];
__device__ __nv_bfloat16 g_QKVbf[MROWS * 3 * DM];
__device__ __nv_bfloat16 g_ATTbf[MROWS * DM];
__device__ __nv_bfloat16 g_Ybf  [MROWS * DM];
__device__ __nv_bfloat16 g_HIDbf[MROWS * FF];
__device__ __nv_bfloat16 g_Zbf  [MROWS * 128];
__device__ float         g_S    [(size_t)768 * NMAX * NMAX];
__device__ __nv_bfloat16 g_Pbf  [(size_t)768 * NMAX * 512];
__device__ __nv_bfloat16 g_Vtbf [(size_t)768 * 64 * 512];

#define OFF_EQKV 0
#define SZ_QKV   (2 * 3 * DM * DM)
#define OFF_EOUT (OFF_EQKV + SZ_QKV)
#define SZ_OUT   (2 * DM * DM)
#define OFF_EW1  (OFF_EOUT + SZ_OUT)
#define SZ_W1    (2 * FF * DM)
#define OFF_EW2  (OFF_EW1 + SZ_W1)
#define SZ_W2    (2 * DM * FF)
#define OFF_DQKV (OFF_EW2 + SZ_W2)
#define OFF_DOUT (OFF_DQKV + SZ_QKV)
#define OFF_DW1  (OFF_DOUT + SZ_OUT)
#define OFF_DW2  (OFF_DW1 + SZ_W1)
#define OFF_PE   (OFF_DW2 + SZ_W2)
#define SZ_PE    (ZZ * DM)
#define OFF_PD   (OFF_PE + SZ_PE)
#define SZ_PD    (DM * 128)
#define WPOOL_SZ (OFF_PD + SZ_PD)
__device__ __nv_bfloat16 g_Wbf[WPOOL_SZ];

__device__ float g_MSK[NMAX * LL];
__device__ float g_meanE[NMAX * DM];
__device__ float g_s[NMAX];
__device__ int   g_Ntot;
__device__ int   g_nresp[BB];
__device__ int   g_next[BB];
__device__ int   g_bidx[NMAX];
__device__ int   g_tidx[NMAX];
__device__ int   g_nodefull[BB * TT];
__device__ int   g_oh[BB * TT];

// ---------------- setup / gather ----------------
__global__ void setup_kernel(const int* __restrict__ tree_lens) {
    if (threadIdx.x == 0 && blockIdx.x == 0) {
        int tot = 0;
        for (int b = 0; b < BB; b++) {
            int tl = tree_lens[b];
            int nr = tl - 1;
            g_nresp[b] = nr;
            int ne = (int)floor((double)nr * 0.05);
            if (ne < 1) ne = 1;
            g_next[b] = ne;
            for (int j = 1; j < tl; j++) { g_bidx[tot] = b; g_tidx[tot] = j; tot++; }
        }
        g_Ntot = tot;
    }
}

__global__ void gather_kernel(const float* __restrict__ emb, const float* __restrict__ amask) {
    int n = blockIdx.x, l = blockIdx.y;
    if (n >= g_Ntot) return;
    int bi = g_bidx[n], ti = g_tidx[n];
    const float* src = emb + (((size_t)bi * TT + ti) * LL + l) * DM;
    __nv_bfloat16* dst = g_Xbf + ((size_t)n * LL + l) * DM;
    for (int d = threadIdx.x; d < DM; d += blockDim.x) dst[d] = __float2bfloat16(src[d]);
    if (threadIdx.x == 0)
        g_MSK[n * LL + l] = amask[((size_t)bi * TT + ti) * LL + l];
}

__global__ void meanE_kernel(const float* __restrict__ emb) {
    int n = blockIdx.x;
    if (n >= g_Ntot) return;
    int d = blockIdx.y * 256 + threadIdx.x;
    int bi = g_bidx[n], ti = g_tidx[n];
    const float* base = emb + ((size_t)bi * TT + ti) * LL * DM;
    float s = 0.f;
    for (int l = 0; l < LL; l++) s += base[(size_t)l * DM + d];
    g_meanE[n * DM + d] = s * (1.f / (float)LL);
}

// ---------------- weight converts ----------------
__global__ void conv_kernel(const float* __restrict__ src, __nv_bfloat16* __restrict__ dst, int cnt) {
    for (int i = blockIdx.x * blockDim.x + threadIdx.x; i < cnt; i += gridDim.x * blockDim.x)
        dst[i] = __float2bfloat16(src[i]);
}
__global__ void conv_pad_kernel(const float* __restrict__ src, __nv_bfloat16* __restrict__ dst) {
    int i = blockIdx.x * blockDim.x + threadIdx.x;
    if (i >= DM * 128) return;
    int r = i >> 7, c = i & 127;
    dst[i] = __float2bfloat16((c < ZZ) ? src[r * ZZ + c] : 0.f);
}

// ---------------- warp-MMA matmul (mma.sync bf16, base-target safe) ----------------
// C[M,N] = A[M,K] @ B[N,K]^T. Block tile 128x64x32, 8 warps (4m x 2n), warp tile 32x32.
// MODE: 0 none / 1 relu / 2 tanh (bf16 out, +bias); 3 QK^T scores (fp32 out); 4 PV (bf16 out)
template <int MODE>
__global__ void __launch_bounds__(256) mm_kernel(
    const __nv_bfloat16* __restrict__ A, long long sAi,
    const __nv_bfloat16* __restrict__ B, long long sBi,
    const float* __restrict__ bias,
    void* __restrict__ Cv, long long sCi,
    int Nreal, int Kdim)
{
    int Nt = g_Ntot;
    int Mreal = (MODE <= 2) ? Nt * LL : Nt;
    int m0 = blockIdx.y * 128;
    if (m0 >= Mreal) return;
    int n0 = blockIdx.x * 64;
    int z = blockIdx.z;
    int l = 0, h = 0;
    const __nv_bfloat16 *Ab, *Bb;
    size_t stA, stB;
    int Ktiles, NvalB;
    if constexpr (MODE <= 2) {
        Ab = A; stA = (size_t)sAi; Bb = B; stB = (size_t)sBi;
        Ktiles = Kdim >> 5; NvalB = Nreal;
    } else if constexpr (MODE == 3) {
        if (n0 >= Nt) return;
        l = z / HH; h = z % HH;
        Ab = A + (size_t)l * (3 * DM) + h * HD;
        Bb = Ab + DM;
        stA = stB = (size_t)LL * 3 * DM;
        Ktiles = 2; NvalB = Nt;               // K = HD = 64
    } else {
        l = z / HH; h = z % HH;
        Ab = A + (size_t)z * NMAX * 512; stA = 512;
        Bb = B + (size_t)z * 64 * 512;   stB = 512;
        Ktiles = (Nt + 31) >> 5; NvalB = 64;  // zero-padded K
    }

    __shared__ __align__(16) __nv_bfloat16 As[2][128][40];
    __shared__ __align__(16) __nv_bfloat16 Bs[2][64][40];

    int tid = threadIdx.x;
    int lane = tid & 31;
    int wid = tid >> 5;
    int wm = wid >> 1;   // 0..3
    int wn = wid & 1;    // 0..1

    float acc[2][4][4];
#pragma unroll
    for (int i = 0; i < 2; i++)
#pragma unroll
        for (int j = 0; j < 4; j++)
#pragma unroll
            for (int q = 0; q < 4; q++) acc[i][j][q] = 0.f;

    // tile loader: 128x32 A (512 16B-chunks), 64x32 B (256 chunks)
    auto load_tile = [&](int kt, int buf) {
#pragma unroll
        for (int i = 0; i < 2; i++) {
            int c = tid + i * 256;
            int r = c >> 2, ko = (c & 3) * 8;
            int m = imin(m0 + r, Mreal - 1);
            cp16(smem_u32(&As[buf][r][ko]), Ab + (size_t)m * stA + (size_t)kt * 32 + ko);
        }
        {
            int r = tid >> 2, ko = (tid & 3) * 8;
            int n = imin(n0 + r, NvalB - 1);
            cp16(smem_u32(&Bs[buf][r][ko]), Bb + (size_t)n * stB + (size_t)kt * 32 + ko);
        }
    };

    load_tile(0, 0);
    cp_commit();

    for (int kt = 0; kt < Ktiles; kt++) {
        int buf = kt & 1;
        if (kt + 1 < Ktiles) {
            load_tile(kt + 1, buf ^ 1);
            cp_commit();
            cp_wait1();
        } else {
            cp_wait0();
        }
        __syncthreads();
#pragma unroll
        for (int ks = 0; ks < 2; ks++) {
            int k0 = ks * 16;
            uint32_t a[2][4], bfr[4][2];
#pragma unroll
            for (int mf = 0; mf < 2; mf++) {
                int row = wm * 32 + mf * 16 + (lane & 7) + ((lane >> 3) & 1) * 8;
                int col = k0 + (lane >> 4) * 8;
                ldmx4(a[mf][0], a[mf][1], a[mf][2], a[mf][3], smem_u32(&As[buf][row][col]));
            }
#pragma unroll
            for (int ng = 0; ng < 2; ng++) {
                int row = wn * 32 + ng * 16 + (lane & 7) + (lane >> 4) * 8;
                int col = k0 + ((lane >> 3) & 1) * 8;
                uint32_t r0, r1, r2, r3;
                ldmx4(r0, r1, r2, r3, smem_u32(&Bs[buf][row][col]));
                bfr[ng * 2][0] = r0;     bfr[ng * 2][1] = r1;
                bfr[ng * 2 + 1][0] = r2; bfr[ng * 2 + 1][1] = r3;
            }
#pragma unroll
            for (int mf = 0; mf < 2; mf++)
#pragma unroll
                for (int nf = 0; nf < 4; nf++)
                    mma16816(acc[mf][nf], a[mf], bfr[nf]);
        }
        __syncthreads();
    }

    // epilogue
#pragma unroll
    for (int mf = 0; mf < 2; mf++) {
#pragma unroll
        for (int nf = 0; nf < 4; nf++) {
            int rbase = m0 + wm * 32 + mf * 16 + (lane >> 2);
            int cbase = n0 + wn * 32 + nf * 8 + (lane & 3) * 2;
#pragma unroll
            for (int q = 0; q < 2; q++) {
                int m = rbase + q * 8;
                if (m >= Mreal) continue;
                float v0 = acc[mf][nf][q * 2];
                float v1 = acc[mf][nf][q * 2 + 1];
                if constexpr (MODE <= 2) {
                    int width = (int)sCi;
                    if (cbase >= width) continue;
                    v0 = (cbase < Nreal)     ? v0 + bias[cbase]     : 0.f;
                    v1 = (cbase + 1 < Nreal) ? v1 + bias[cbase + 1] : 0.f;
                    if (MODE == 1) { v0 = fmaxf(v0, 0.f); v1 = fmaxf(v1, 0.f); }
                    if (MODE == 2) { v0 = tanhf(v0); v1 = tanhf(v1); }
                    __nv_bfloat16* Crow = (__nv_bfloat16*)Cv + (size_t)m * width + cbase;
                    *(__nv_bfloat162*)Crow = __floats2bfloat162_rn(v0, v1);
                } else if constexpr (MODE == 3) {
                    float* Crow = (float*)Cv + (size_t)z * NMAX * NMAX + (size_t)m * NMAX;
                    if (cbase < Mreal)     Crow[cbase]     = v0 * 0.125f + g_MSK[cbase * LL + l];
                    if (cbase + 1 < Mreal) Crow[cbase + 1] = v1 * 0.125f + g_MSK[(cbase + 1) * LL + l];
                } else {
                    __nv_bfloat16* Crow = (__nv_bfloat16*)Cv +
                        ((size_t)m * LL + l) * DM + h * HD + cbase;
                    *(__nv_bfloat162*)Crow = __floats2bfloat162_rn(v0, v1);
                }
            }
        }
    }
}

// ---------------- softmax: S fp32 -> P bf16 (zero-padded to ceil64) ----------------
__global__ void softmax_kernel() {
    int n = blockIdx.x, z = blockIdx.y;
    int Nt = g_Ntot;
    if (n >= Nt) return;
    int Kc = (Nt + 63) & ~63;
    const float* srow = g_S + (size_t)z * NMAX * NMAX + (size_t)n * NMAX;
    __nv_bfloat16* prow = g_Pbf + (size_t)z * NMAX * 512 + (size_t)n * 512;
    int t = threadIdx.x; // 128
    float v[4];
    float mx = -INFINITY;
#pragma unroll
    for (int i = 0; i < 4; i++) {
        int j = t + 128 * i;
        v[i] = (j < Nt) ? srow[j] : -INFINITY;
        mx = fmaxf(mx, v[i]);
    }
    __shared__ float red[128];
    red[t] = mx; __syncthreads();
    for (int s = 64; s > 0; s >>= 1) { if (t < s) red[t] = fmaxf(red[t], red[t + s]); __syncthreads(); }
    mx = red[0]; __syncthreads();
    float sum = 0.f;
#pragma unroll
    for (int i = 0; i < 4; i++) {
        int j = t + 128 * i;
        v[i] = (j < Nt) ? __expf(v[i] - mx) : 0.f;
        sum += v[i];
    }
    red[t] = sum; __syncthreads();
    for (int s = 64; s > 0; s >>= 1) { if (t < s) red[t] += red[t + s]; __syncthreads(); }
    float inv = 1.f / red[0];
#pragma unroll
    for (int i = 0; i < 4; i++) {
        int j = t + 128 * i;
        if (j < Kc) prow[j] = __float2bfloat16(v[i] * inv);
    }
}

// ---------------- V transpose: Vt[z][d][m] (zero-padded in m) ----------------
__global__ void vt_kernel() {
    int z = blockIdx.y;
    int m0 = blockIdx.x * 32;
    int l = z / HH, h = z % HH;
    int Nt = g_Ntot;
    __shared__ __nv_bfloat16 s[32][80];
    int t = threadIdx.x; // 256
    {
        int mi = t >> 3, c = t & 7;
        int m = m0 + mi;
        uint4 val = make_uint4(0, 0, 0, 0);
        if (m < Nt)
            val = *(const uint4*)(g_QKVbf + ((size_t)m * LL + l) * (3 * DM) + 2 * DM + h * HD + c * 8);
        *(uint4*)&s[mi][c * 8] = val;
    }
    __syncthreads();
    {
        int d = t >> 2, mo = (t & 3) * 8;
        __nv_bfloat16 tmp[8];
#pragma unroll
        for (int k = 0; k < 8; k++) tmp[k] = s[mo + k][d];
        *(uint4*)(g_Vtbf + (size_t)z * 64 * 512 + (size_t)d * 512 + m0 + mo) = *(uint4*)tmp;
    }
}

// ---------------- residual + LayerNorm ----------------
__global__ void add_ln_kernel(__nv_bfloat16* __restrict__ X, const __nv_bfloat16* __restrict__ Yv,
                              const float* __restrict__ g, const float* __restrict__ b) {
    int row = blockIdx.x;
    if (row >= g_Ntot * LL) return;
    __nv_bfloat16* x = X + (size_t)row * DM;
    const __nv_bfloat16* y = Yv + (size_t)row * DM;
    int t = threadIdx.x;
    float v[3], s = 0.f, s2 = 0.f;
#pragma unroll
    for (int i = 0; i < 3; i++) {
        int d = t + 256 * i;
        float u = __bfloat162float(x[d]) + __bfloat162float(y[d]);
        v[i] = u; s += u; s2 += u * u;
    }
    __shared__ float rs[256], rs2[256];
    rs[t] = s; rs2[t] = s2; __syncthreads();
    for (int st = 128; st > 0; st >>= 1) {
        if (t < st) { rs[t] += rs[t + st]; rs2[t] += rs2[t + st]; }
        __syncthreads();
    }
    float mean = rs[0] * (1.f / (float)DM);
    float var = rs2[0] * (1.f / (float)DM) - mean * mean;
    float inv = rsqrtf(var + 1e-5f);
#pragma unroll
    for (int i = 0; i < 3; i++) {
        int d = t + 256 * i;
        x[d] = __float2bfloat16((v[i] - mean) * inv * g[d] + b[d]);
    }
}

// ---------------- anomaly ----------------
__global__ void anomaly_kernel() {
    int n = blockIdx.x;
    if (n >= g_Ntot) return;
    int t = threadIdx.x;
    float acc = 0.f;
#pragma unroll
    for (int i = 0; i < 3; i++) {
        int d = t + 256 * i;
        float m = 0.f;
        for (int l = 0; l < LL; l++)
            m += __bfloat162float(g_Xbf[((size_t)n * LL + l) * DM + d]);
        m *= (1.f / (float)LL);
        float diff = m - g_meanE[n * DM + d];
        acc += diff * diff;
    }
    __shared__ float red[256];
    red[t] = acc; __syncthreads();
    for (int s = 128; s > 0; s >>= 1) { if (t < s) red[t] += red[t + s]; __syncthreads(); }
    if (t == 0) g_s[n] = red[0];
}

// ---------------- selection ----------------
__global__ void select_kernel() {
    int b = threadIdx.x;
    if (b >= BB) return;
    int nr = g_nresp[b];
    int ne = g_next[b];
    bool used[TT];
    int ohf[TT];
#pragma unroll
    for (int j = 0; j < TT; j++) { used[j] = false; ohf[j] = 0; }
    ohf[0] = 1;
    g_nodefull[b * TT + 0] = 0;
    for (int i = 0; i < TT - 1; i++) {
        int node = 0;
        if (i < ne) {
            float best = INFINITY; int bj = 0;
            for (int j = 0; j < nr; j++) {
                if (!used[j] && g_s[j] < best) { best = g_s[j]; bj = j; }
            }
            used[bj] = true;
            node = bj + 1;
            ohf[node] = 1;
        }
        g_nodefull[b * TT + i + 1] = node;
    }
    for (int t = 0; t < TT; t++) g_oh[b * TT + t] = ohf[t];
}

// ---------------- output writers ----------------
__global__ void out_small_kernel(float* __restrict__ out, long long off_oh,
                                 long long off_sc, long long off_tl, int has_sc) {
    int t = blockIdx.x * blockDim.x + threadIdx.x;
    if (t < BB * TT) out[off_oh + t] = (float)g_oh[t];
    else if (t < BB * TT + BB) out[off_tl + (t - BB * TT)] = (float)(1 + g_next[t - BB * TT]);
    else if (t == BB * TT + BB && has_sc) out[off_sc] = 0.f;
}
__global__ void ext_mask_kernel(float* __restrict__ out, long long off) {
    int bt = blockIdx.x;
    out[off + (size_t)bt * LL + threadIdx.x] = (float)g_oh[bt];
}
__global__ void new_msk_kernel(const float* __restrict__ amask,
                               float* __restrict__ out, long long off) {
    int bt = blockIdx.x;
    int b = bt >> 5, t = bt & 31;
    int node = g_nodefull[bt];
    float valid = (t == 0 || (t - 1) < g_next[b]) ? 1.f : 0.f;
    out[off + (size_t)bt * LL + threadIdx.x] =
        amask[((size_t)b * TT + node) * LL + threadIdx.x] * valid;
}
__global__ void new_emb_kernel(const float* __restrict__ emb,
                               float* __restrict__ out, long long off) {
    int bt = blockIdx.x / 192;
    int r = (blockIdx.x % 192) * 256 + threadIdx.x;
    int b = bt >> 5;
    int node = g_nodefull[bt];
    out[off + (size_t)bt * (LL * DM) + r] =
        emb[((size_t)b * TT + node) * (LL * DM) + r];
}

// ---------------- host ----------------
static void run_layer(__nv_bfloat16* pW, int qkvOff, int outOff, int w1Off, int w2Off,
                      const float* qkvb, const float* outb,
                      const float* g1, const float* b1,
                      const float* c1, const float* c2,
                      const float* g2, const float* b2,
                      __nv_bfloat16* pX, __nv_bfloat16* pQKV, __nv_bfloat16* pATT,
                      __nv_bfloat16* pY, __nv_bfloat16* pHID,
                      float* pS, __nv_bfloat16* pP, __nv_bfloat16* pVt) {
    const int GY = 248;  // ceil(NMAX*64 / 128)
    mm_kernel<0><<<dim3(36, GY), 256>>>(pX, DM, pW + qkvOff, DM, qkvb, pQKV, 3 * DM, 3 * DM, DM);
    mm_kernel<3><<<dim3(8, 4, 768), 256>>>(pQKV, 0, nullptr, 0, nullptr, pS, 0, 0, HD);
    softmax_kernel<<<dim3(NMAX, 768), 128>>>();
    vt_kernel<<<dim3(16, 768), 256>>>();
    mm_kernel<4><<<dim3(1, 4, 768), 256>>>(pP, 0, pVt, 0, nullptr, pATT, 0, 0, 0);
    mm_kernel<0><<<dim3(12, GY), 256>>>(pATT, DM, pW + outOff, DM, outb, pY, DM, DM, DM);
    add_ln_kernel<<<NMAX * LL, 256>>>(pX, pY, g1, b1);
    mm_kernel<1><<<dim3(32, GY), 256>>>(pX, DM, pW + w1Off, DM, c1, pHID, FF, FF, DM);
    mm_kernel<0><<<dim3(12, GY), 256>>>(pHID, FF, pW + w2Off, FF, c2, pY, DM, DM, FF);
    add_ln_kernel<<<NMAX * LL, 256>>>(pX, pY, g2, b2);
}

extern "C" void kernel_launch(void* const* d_in, const int* in_sizes, int n_in,
                              void* d_out, int out_size) {
    const int*   tree_lens = (const int*)d_in[0];
    const float* emb       = (const float*)d_in[1];
    const float* amask     = (const float*)d_in[2];
    const float* P[28];
    for (int i = 3; i < 31; i++) P[i - 3] = (const float*)d_in[i];
    float* out = (float*)d_out;

    __nv_bfloat16 *pX, *pQKV, *pATT, *pY, *pHID, *pZ, *pW, *pP, *pVt;
    float *pS;
    cudaGetSymbolAddress((void**)&pX, g_Xbf);
    cudaGetSymbolAddress((void**)&pQKV, g_QKVbf);
    cudaGetSymbolAddress((void**)&pATT, g_ATTbf);
    cudaGetSymbolAddress((void**)&pY, g_Ybf);
    cudaGetSymbolAddress((void**)&pHID, g_HIDbf);
    cudaGetSymbolAddress((void**)&pZ, g_Zbf);
    cudaGetSymbolAddress((void**)&pW, g_Wbf);
    cudaGetSymbolAddress((void**)&pS, g_S);
    cudaGetSymbolAddress((void**)&pP, g_Pbf);
    cudaGetSymbolAddress((void**)&pVt, g_Vtbf);

    const long long NE_ELEMS = (long long)BB * TT * LL * DM;
    const long long TOT_W = 512 + 32768 + 1 + 16 + NE_ELEMS + 32768;
    int has_sc = ((long long)out_size == TOT_W - 1) ? 0 : 1;
    long long off_oh = 0;
    long long off_em = 512;
    long long off_sc = 512 + 32768;
    long long off_tl = off_sc + (has_sc ? 1 : 0);
    long long off_ne = off_tl + 16;
    long long off_nm = off_ne + NE_ELEMS;

    setup_kernel<<<1, 32>>>(tree_lens);
    gather_kernel<<<dim3(NMAX, LL), 256>>>(emb, amask);
    meanE_kernel<<<dim3(NMAX, 3), 256>>>(emb);

    conv_kernel<<<512, 256>>>(P[0],  pW + OFF_EQKV, SZ_QKV);
    conv_kernel<<<512, 256>>>(P[2],  pW + OFF_EOUT, SZ_OUT);
    conv_kernel<<<512, 256>>>(P[6],  pW + OFF_EW1,  SZ_W1);
    conv_kernel<<<512, 256>>>(P[8],  pW + OFF_EW2,  SZ_W2);
    conv_kernel<<<512, 256>>>(P[12], pW + OFF_DQKV, SZ_QKV);
    conv_kernel<<<512, 256>>>(P[14], pW + OFF_DOUT, SZ_OUT);
    conv_kernel<<<512, 256>>>(P[18], pW + OFF_DW1,  SZ_W1);
    conv_kernel<<<512, 256>>>(P[20], pW + OFF_DW2,  SZ_W2);
    conv_kernel<<<128, 256>>>(P[24], pW + OFF_PE,   SZ_PE);
    conv_pad_kernel<<<(DM * 128 + 255) / 256, 256>>>(P[26], pW + OFF_PD);

    const int LQKV = 3 * DM * DM, LOUT = DM * DM, LW1 = FF * DM, LW2 = DM * FF;
    for (int i = 0; i < 2; i++)
        run_layer(pW, OFF_EQKV + i * LQKV, OFF_EOUT + i * LOUT,
                  OFF_EW1 + i * LW1, OFF_EW2 + i * LW2,
                  P[1] + (size_t)i * 3 * DM, P[3] + (size_t)i * DM,
                  P[4] + (size_t)i * DM, P[5] + (size_t)i * DM,
                  P[7] + (size_t)i * FF, P[9] + (size_t)i * DM,
                  P[10] + (size_t)i * DM, P[11] + (size_t)i * DM,
                  pX, pQKV, pATT, pY, pHID, pS, pP, pVt);

    // z = tanh(h @ pe^T + pe_b)  [out width 128, cols 100..127 zeroed]
    mm_kernel<2><<<dim3(2, 248), 256>>>(pX, DM, pW + OFF_PE, DM, P[25], pZ, 128, ZZ, DM);
    // zd = tanh(z @ pd^T + pd_b) [K=128 with zero-padded weights]
    mm_kernel<2><<<dim3(12, 248), 256>>>(pZ, 128, pW + OFF_PD, 128, P[27], pX, DM, DM, 128);

    for (int i = 0; i < 2; i++)
        run_layer(pW, OFF_DQKV + i * LQKV, OFF_DOUT + i * LOUT,
                  OFF_DW1 + i * LW1, OFF_DW2 + i * LW2,
                  P[13] + (size_t)i * 3 * DM, P[15] + (size_t)i * DM,
                  P[16] + (size_t)i * DM, P[17] + (size_t)i * DM,
                  P[19] + (size_t)i * FF, P[21] + (size_t)i * DM,
                  P[22] + (size_t)i * DM, P[23] + (size_t)i * DM,
                  pX, pQKV, pATT, pY, pHID, pS, pP, pVt);

    anomaly_kernel<<<NMAX, 256>>>();
    select_kernel<<<1, 32>>>();

    out_small_kernel<<<3, 256>>>(out, off_oh, off_sc, off_tl, has_sc);
    ext_mask_kernel<<<BB * TT, LL>>>(out, off_em);
    new_msk_kernel<<<BB * TT, LL>>>(amask, out, off_nm);
    new_emb_kernel<<<BB * TT * 192, 256>>>(emb, out, off_ne);
}

// round 5
// speedup vs baseline: 10.9992x; 1.3049x over previous
#include <cuda_runtime.h>
#include <cuda_bf16.h>
#include <math.h>
#include <stdint.h>

#define BB   16
#define TT   32
#define LL   64
#define DM   768
#define HH   12
#define HD   64
#define FF   2048
#define ZZ   100
#define NMAX 496
#define MROWS (NMAX * LL)

// ---------------- helpers ----------------
__device__ __forceinline__ uint32_t smem_u32(const void* p) {
    uint32_t a;
    asm("{ .reg .u64 t; cvta.to.shared.u64 t, %1; cvt.u32.u64 %0, t; }" : "=r"(a) : "l"(p));
    return a;
}
__device__ __forceinline__ void cp16(uint32_t dst, const void* src) {
    asm volatile("cp.async.cg.shared.global [%0], [%1], 16;" :: "r"(dst), "l"(src));
}
__device__ __forceinline__ void cp_commit() { asm volatile("cp.async.commit_group;" ::: "memory"); }
__device__ __forceinline__ void cp_wait0()  { asm volatile("cp.async.wait_group 0;" ::: "memory"); }
__device__ __forceinline__ void cp_wait1()  { asm volatile("cp.async.wait_group 1;" ::: "memory"); }
__device__ __forceinline__ void ldmx4(uint32_t& r0, uint32_t& r1, uint32_t& r2, uint32_t& r3,
                                      uint32_t addr) {
    asm volatile("ldmatrix.sync.aligned.m8n8.x4.shared.b16 {%0,%1,%2,%3}, [%4];"
                 : "=r"(r0), "=r"(r1), "=r"(r2), "=r"(r3) : "r"(addr));
}
__device__ __forceinline__ void ldmx4t(uint32_t& r0, uint32_t& r1, uint32_t& r2, uint32_t& r3,
                                       uint32_t addr) {
    asm volatile("ldmatrix.sync.aligned.m8n8.x4.trans.shared.b16 {%0,%1,%2,%3}, [%4];"
                 : "=r"(r0), "=r"(r1), "=r"(r2), "=r"(r3) : "r"(addr));
}
__device__ __forceinline__ void mma16816(float* c, const uint32_t* a, const uint32_t* b) {
    asm volatile("mma.sync.aligned.m16n8k16.row.col.f32.bf16.bf16.f32 "
                 "{%0,%1,%2,%3}, {%4,%5,%6,%7}, {%8,%9}, {%0,%1,%2,%3};"
                 : "+f"(c[0]), "+f"(c[1]), "+f"(c[2]), "+f"(c[3])
                 : "r"(a[0]), "r"(a[1]), "r"(a[2]), "r"(a[3]), "r"(b[0]), "r"(b[1]));
}
__device__ __forceinline__ int imin(int a, int b) { return a < b ? a : b; }

// fast exp on the FMA pipe (avoids MUFU serialization); x <= 0 expected
__device__ __forceinline__ float fexp(float x) {
    float t = x * 1.44269504f;
    t = fmaxf(t, -125.0f);
    float e = floorf(t);
    float f = t - e;
    float p = 1.0f + f * (0.69314718f + f * (0.24022651f + f * (0.05550411f +
              f * (0.00961813f + f * 0.00133336f))));
    return p * __int_as_float(((int)e + 127) << 23);
}

// ---------------- device scratch ----------------
__device__ __nv_bfloat16 g_Xbf  [MROWS * DM];
__device__ __nv_bfloat16 g_QKVbf[MROWS * 3 * DM];
__device__ __nv_bfloat16 g_ATTbf[MROWS * DM];
__device__ __nv_bfloat16 g_Ybf  [MROWS * DM];
__device__ __nv_bfloat16 g_HIDbf[MROWS * FF];
__device__ __nv_bfloat16 g_Zbf  [MROWS * 128];

#define OFF_EQKV 0
#define SZ_QKV   (2 * 3 * DM * DM)
#define OFF_EOUT (OFF_EQKV + SZ_QKV)
#define SZ_OUT   (2 * DM * DM)
#define OFF_EW1  (OFF_EOUT + SZ_OUT)
#define SZ_W1    (2 * FF * DM)
#define OFF_EW2  (OFF_EW1 + SZ_W1)
#define SZ_W2    (2 * DM * FF)
#define OFF_DQKV (OFF_EW2 + SZ_W2)
#define OFF_DOUT (OFF_DQKV + SZ_QKV)
#define OFF_DW1  (OFF_DOUT + SZ_OUT)
#define OFF_DW2  (OFF_DW1 + SZ_W1)
#define OFF_PE   (OFF_DW2 + SZ_W2)
#define SZ_PE    (ZZ * DM)
#define OFF_PD   (OFF_PE + SZ_PE)
#define SZ_PD    (DM * 128)
#define WPOOL_SZ (OFF_PD + SZ_PD)
__device__ __nv_bfloat16 g_Wbf[WPOOL_SZ];

__device__ float g_MSK[NMAX * LL];
__device__ float g_meanE[NMAX * DM];
__device__ float g_s[NMAX];
__device__ int   g_Ntot;
__device__ int   g_nresp[BB];
__device__ int   g_next[BB];
__device__ int   g_bidx[NMAX];
__device__ int   g_tidx[NMAX];
__device__ int   g_nodefull[BB * TT];
__device__ int   g_oh[BB * TT];

// ---------------- setup / gather ----------------
__global__ void setup_kernel(const int* __restrict__ tree_lens) {
    if (threadIdx.x == 0 && blockIdx.x == 0) {
        int tot = 0;
        for (int b = 0; b < BB; b++) {
            int tl = tree_lens[b];
            int nr = tl - 1;
            g_nresp[b] = nr;
            int ne = (int)floor((double)nr * 0.05);
            if (ne < 1) ne = 1;
            g_next[b] = ne;
            for (int j = 1; j < tl; j++) { g_bidx[tot] = b; g_tidx[tot] = j; tot++; }
        }
        g_Ntot = tot;
    }
}

__global__ void gather_kernel(const float* __restrict__ emb, const float* __restrict__ amask) {
    int n = blockIdx.x, l = blockIdx.y;
    if (n >= g_Ntot) return;
    int bi = g_bidx[n], ti = g_tidx[n];
    const float* src = emb + (((size_t)bi * TT + ti) * LL + l) * DM;
    __nv_bfloat16* dst = g_Xbf + ((size_t)n * LL + l) * DM;
    for (int d = threadIdx.x; d < DM; d += blockDim.x) dst[d] = __float2bfloat16(src[d]);
    if (threadIdx.x == 0)
        g_MSK[n * LL + l] = amask[((size_t)bi * TT + ti) * LL + l];
}

__global__ void meanE_kernel(const float* __restrict__ emb) {
    int n = blockIdx.x;
    if (n >= g_Ntot) return;
    int d = blockIdx.y * 256 + threadIdx.x;
    int bi = g_bidx[n], ti = g_tidx[n];
    const float* base = emb + ((size_t)bi * TT + ti) * LL * DM;
    float s = 0.f;
    for (int l = 0; l < LL; l++) s += base[(size_t)l * DM + d];
    g_meanE[n * DM + d] = s * (1.f / (float)LL);
}

// ---------------- weight converts ----------------
__global__ void conv_kernel(const float* __restrict__ src, __nv_bfloat16* __restrict__ dst, int cnt) {
    for (int i = blockIdx.x * blockDim.x + threadIdx.x; i < cnt; i += gridDim.x * blockDim.x)
        dst[i] = __float2bfloat16(src[i]);
}
__global__ void conv_pad_kernel(const float* __restrict__ src, __nv_bfloat16* __restrict__ dst) {
    int i = blockIdx.x * blockDim.x + threadIdx.x;
    if (i >= DM * 128) return;
    int r = i >> 7, c = i & 127;
    dst[i] = __float2bfloat16((c < ZZ) ? src[r * ZZ + c] : 0.f);
}

// ---------------- warp-MMA GEMM: 128x128x32 block, warp tile 32x64 ----------------
// C[M,N] = A[M,K] @ B[N,K]^T (+bias, act). MODE: 0 none / 1 relu / 2 tanh
template <int MODE>
__global__ void __launch_bounds__(256) mm_kernel(
    const __nv_bfloat16* __restrict__ A, long long sAi,
    const __nv_bfloat16* __restrict__ B, long long sBi,
    const float* __restrict__ bias,
    __nv_bfloat16* __restrict__ C, long long sCi,
    int Nreal, int Kdim)
{
    int Mreal = g_Ntot * LL;
    int m0 = blockIdx.y * 128;
    if (m0 >= Mreal) return;
    int n0 = blockIdx.x * 128;
    size_t stA = (size_t)sAi, stB = (size_t)sBi;
    int Ktiles = Kdim >> 5;

    __shared__ __align__(16) __nv_bfloat16 As[2][128][40];
    __shared__ __align__(16) __nv_bfloat16 Bs[2][128][40];

    int tid = threadIdx.x;
    int lane = tid & 31;
    int w = tid >> 5;
    int wm = w >> 1;   // 0..3 (32 rows each)
    int wn = w & 1;    // 0..1 (64 cols each)

    float acc[2][8][4];
#pragma unroll
    for (int i = 0; i < 2; i++)
#pragma unroll
        for (int j = 0; j < 8; j++)
#pragma unroll
            for (int q = 0; q < 4; q++) acc[i][j][q] = 0.f;

    auto load_tile = [&](int kt, int buf) {
#pragma unroll
        for (int i = 0; i < 2; i++) {
            int c = tid + i * 256;
            int r = c >> 2, ko = (c & 3) * 8;
            int m = imin(m0 + r, Mreal - 1);
            cp16(smem_u32(&As[buf][r][ko]), A + (size_t)m * stA + (size_t)kt * 32 + ko);
        }
#pragma unroll
        for (int i = 0; i < 2; i++) {
            int c = tid + i * 256;
            int r = c >> 2, ko = (c & 3) * 8;
            int n = imin(n0 + r, Nreal - 1);
            cp16(smem_u32(&Bs[buf][r][ko]), B + (size_t)n * stB + (size_t)kt * 32 + ko);
        }
    };

    load_tile(0, 0);
    cp_commit();

    for (int kt = 0; kt < Ktiles; kt++) {
        int buf = kt & 1;
        if (kt + 1 < Ktiles) {
            load_tile(kt + 1, buf ^ 1);
            cp_commit();
            cp_wait1();
        } else {
            cp_wait0();
        }
        __syncthreads();
#pragma unroll
        for (int ks = 0; ks < 2; ks++) {
            int k0 = ks * 16;
            uint32_t a[2][4], bb[8][2];
#pragma unroll
            for (int mf = 0; mf < 2; mf++) {
                int row = wm * 32 + mf * 16 + (lane & 7) + ((lane >> 3) & 1) * 8;
                int col = k0 + (lane >> 4) * 8;
                ldmx4(a[mf][0], a[mf][1], a[mf][2], a[mf][3], smem_u32(&As[buf][row][col]));
            }
#pragma unroll
            for (int ng = 0; ng < 4; ng++) {
                int row = wn * 64 + ng * 16 + (lane & 7) + (lane >> 4) * 8;
                int col = k0 + ((lane >> 3) & 1) * 8;
                uint32_t r0, r1, r2, r3;
                ldmx4(r0, r1, r2, r3, smem_u32(&Bs[buf][row][col]));
                bb[ng * 2][0] = r0;     bb[ng * 2][1] = r1;
                bb[ng * 2 + 1][0] = r2; bb[ng * 2 + 1][1] = r3;
            }
#pragma unroll
            for (int mf = 0; mf < 2; mf++)
#pragma unroll
                for (int nf = 0; nf < 8; nf++)
                    mma16816(acc[mf][nf], a[mf], bb[nf]);
        }
        __syncthreads();
    }

    int width = (int)sCi;
#pragma unroll
    for (int mf = 0; mf < 2; mf++) {
#pragma unroll
        for (int nf = 0; nf < 8; nf++) {
            int rbase = m0 + wm * 32 + mf * 16 + (lane >> 2);
            int cbase = n0 + wn * 64 + nf * 8 + (lane & 3) * 2;
            if (cbase >= width) continue;
#pragma unroll
            for (int q = 0; q < 2; q++) {
                int m = rbase + q * 8;
                if (m >= Mreal) continue;
                float v0 = (cbase < Nreal)     ? acc[mf][nf][q * 2]     + bias[cbase]     : 0.f;
                float v1 = (cbase + 1 < Nreal) ? acc[mf][nf][q * 2 + 1] + bias[cbase + 1] : 0.f;
                if (MODE == 1) { v0 = fmaxf(v0, 0.f); v1 = fmaxf(v1, 0.f); }
                if (MODE == 2) { v0 = tanhf(v0); v1 = tanhf(v1); }
                *(__nv_bfloat162*)(C + (size_t)m * width + cbase) = __floats2bfloat162_rn(v0, v1);
            }
        }
    }
}

// ---------------- fused attention: per (l,h,64-row tile) ----------------
// Phase1: S = Q@K^T * 0.125 + mask -> smem bf16 [64][520]
// Phase2: in-place row softmax (fast exp)
// Phase3: O = P@V (ldmatrix.trans on V) -> g_ATTbf
#define SP_STRIDE 520
#define SM_SP  0
#define SM_Q   (64 * SP_STRIDE * 2)                  // 66560
#define SM_KV  (SM_Q + 64 * 72 * 2)                  // +9216
#define SM_MSK (SM_KV + 2 * 64 * 72 * 2)             // +18432
#define ATTN_SMEM (SM_MSK + 512 * 4)                 // 96256

__global__ void __launch_bounds__(256) attn_kernel(
    const __nv_bfloat16* __restrict__ QKV, __nv_bfloat16* __restrict__ ATT)
{
    int Nt = g_Ntot;
    int n0 = blockIdx.x * 64;
    if (n0 >= Nt) return;
    int z = blockIdx.y;
    int l = z / HH, h = z % HH;
    int Kc = (Nt + 63) & ~63;
    int Mtiles = Kc >> 6;

    extern __shared__ char smem[];
    __nv_bfloat16* SP = (__nv_bfloat16*)(smem + SM_SP);
    __nv_bfloat16* Qs = (__nv_bfloat16*)(smem + SM_Q);
    __nv_bfloat16* KV = (__nv_bfloat16*)(smem + SM_KV);
    float*        msk = (float*)(smem + SM_MSK);

    int tid = threadIdx.x;
    int lane = tid & 31;
    int w = tid >> 5;
    int wm = w >> 1;   // 0..3
    int wn = w & 1;

    // mask (pad cols -> -1e30)
    for (int j = tid; j < 512; j += 256)
        msk[j] = (j < Nt) ? g_MSK[j * LL + l] : -1e30f;

    // Q tile 64x64 (rows clamped)
#pragma unroll
    for (int i = 0; i < 2; i++) {
        int c = tid + i * 256;
        int r = c >> 3, co = (c & 7) * 8;
        int n = imin(n0 + r, Nt - 1);
        cp16(smem_u32(&Qs[r * 72 + co]), QKV + ((size_t)n * LL + l) * (3 * DM) + h * HD + co);
    }

    auto load_kv = [&](int mt, int buf, int which) {
#pragma unroll
        for (int i = 0; i < 2; i++) {
            int c = tid + i * 256;
            int r = c >> 3, co = (c & 7) * 8;
            int m = imin(mt * 64 + r, Nt - 1);
            cp16(smem_u32(&KV[(buf * 64 + r) * 72 + co]),
                 QKV + ((size_t)m * LL + l) * (3 * DM) + which * DM + h * HD + co);
        }
    };

    load_kv(0, 0, 1);
    cp_commit();

    // ---- phase 1: scores ----
    for (int mt = 0; mt < Mtiles; mt++) {
        int buf = mt & 1;
        if (mt + 1 < Mtiles) { load_kv(mt + 1, buf ^ 1, 1); cp_commit(); cp_wait1(); }
        else cp_wait0();
        __syncthreads();

        float acc[4][4];
#pragma unroll
        for (int j = 0; j < 4; j++)
#pragma unroll
            for (int q = 0; q < 4; q++) acc[j][q] = 0.f;

#pragma unroll
        for (int ks = 0; ks < 4; ks++) {
            int k0 = ks * 16;
            uint32_t a[4], bb[4][2];
            {
                int row = wm * 16 + (lane & 7) + ((lane >> 3) & 1) * 8;
                int col = k0 + (lane >> 4) * 8;
                ldmx4(a[0], a[1], a[2], a[3], smem_u32(&Qs[row * 72 + col]));
            }
#pragma unroll
            for (int ng = 0; ng < 2; ng++) {
                int row = wn * 32 + ng * 16 + (lane & 7) + (lane >> 4) * 8;
                int col = k0 + ((lane >> 3) & 1) * 8;
                uint32_t r0, r1, r2, r3;
                ldmx4(r0, r1, r2, r3, smem_u32(&KV[(buf * 64 + row) * 72 + col]));
                bb[ng * 2][0] = r0;     bb[ng * 2][1] = r1;
                bb[ng * 2 + 1][0] = r2; bb[ng * 2 + 1][1] = r3;
            }
#pragma unroll
            for (int nf = 0; nf < 4; nf++) mma16816(acc[nf], a, bb[nf]);
        }
        // write S frags with scale + mask
        int rbase = wm * 16 + (lane >> 2);
#pragma unroll
        for (int nf = 0; nf < 4; nf++) {
            int cl = wn * 32 + nf * 8 + (lane & 3) * 2;
            int gc = mt * 64 + cl;
            float m0v = msk[gc], m1v = msk[gc + 1];
#pragma unroll
            for (int q = 0; q < 2; q++) {
                int r = rbase + q * 8;
                float v0 = acc[nf][q * 2]     * 0.125f + m0v;
                float v1 = acc[nf][q * 2 + 1] * 0.125f + m1v;
                *(__nv_bfloat162*)&SP[r * SP_STRIDE + gc] = __floats2bfloat162_rn(v0, v1);
            }
        }
        __syncthreads();
    }

    // ---- phase 2: softmax (warp w owns rows w*8..w*8+7) ----
    {
        int cnt = Kc >> 5;  // <= 16
        for (int rr = 0; rr < 8; rr++) {
            int r = w * 8 + rr;
            float vals[16];
            float mx = -INFINITY;
            for (int i = 0; i < cnt; i++) {
                vals[i] = __bfloat162float(SP[r * SP_STRIDE + lane + i * 32]);
                mx = fmaxf(mx, vals[i]);
            }
#pragma unroll
            for (int o = 16; o > 0; o >>= 1) mx = fmaxf(mx, __shfl_xor_sync(0xffffffff, mx, o));
            float sum = 0.f;
            for (int i = 0; i < cnt; i++) { vals[i] = fexp(vals[i] - mx); sum += vals[i]; }
#pragma unroll
            for (int o = 16; o > 0; o >>= 1) sum += __shfl_xor_sync(0xffffffff, sum, o);
            float inv = 1.f / sum;
            for (int i = 0; i < cnt; i++)
                SP[r * SP_STRIDE + lane + i * 32] = __float2bfloat16(vals[i] * inv);
        }
    }
    __syncthreads();

    // ---- phase 3: O = P @ V ----
    float oacc[4][4];
#pragma unroll
    for (int j = 0; j < 4; j++)
#pragma unroll
        for (int q = 0; q < 4; q++) oacc[j][q] = 0.f;

    load_kv(0, 0, 2);
    cp_commit();

    for (int mt = 0; mt < Mtiles; mt++) {
        int buf = mt & 1;
        if (mt + 1 < Mtiles) { load_kv(mt + 1, buf ^ 1, 2); cp_commit(); cp_wait1(); }
        else cp_wait0();
        __syncthreads();

#pragma unroll
        for (int ks = 0; ks < 4; ks++) {
            int mk0 = mt * 64 + ks * 16;
            uint32_t a[4], bb[4][2];
            {
                int row = wm * 16 + (lane & 7) + ((lane >> 3) & 1) * 8;
                int col = mk0 + (lane >> 4) * 8;
                ldmx4(a[0], a[1], a[2], a[3], smem_u32(&SP[row * SP_STRIDE + col]));
            }
#pragma unroll
            for (int ng = 0; ng < 2; ng++) {
                int vrow = ks * 16 + (lane & 7) + ((lane >> 3) & 1) * 8;
                int vcol = wn * 32 + ng * 16 + (lane >> 4) * 8;
                uint32_t r0, r1, r2, r3;
                ldmx4t(r0, r1, r2, r3, smem_u32(&KV[(buf * 64 + vrow) * 72 + vcol]));
                bb[ng * 2][0] = r0;     bb[ng * 2][1] = r1;
                bb[ng * 2 + 1][0] = r2; bb[ng * 2 + 1][1] = r3;
            }
#pragma unroll
            for (int nf = 0; nf < 4; nf++) mma16816(oacc[nf], a, bb[nf]);
        }
        __syncthreads();
    }

    // write O
    int rbase = wm * 16 + (lane >> 2);
#pragma unroll
    for (int nf = 0; nf < 4; nf++) {
        int c = wn * 32 + nf * 8 + (lane & 3) * 2;
#pragma unroll
        for (int q = 0; q < 2; q++) {
            int n = n0 + rbase + q * 8;
            if (n < Nt) {
                __nv_bfloat16* row = ATT + ((size_t)n * LL + l) * DM + h * HD + c;
                *(__nv_bfloat162*)row =
                    __floats2bfloat162_rn(oacc[nf][q * 2], oacc[nf][q * 2 + 1]);
            }
        }
    }
}

// ---------------- residual + LayerNorm ----------------
__global__ void add_ln_kernel(__nv_bfloat16* __restrict__ X, const __nv_bfloat16* __restrict__ Yv,
                              const float* __restrict__ g, const float* __restrict__ b) {
    int row = blockIdx.x;
    if (row >= g_Ntot * LL) return;
    __nv_bfloat16* x = X + (size_t)row * DM;
    const __nv_bfloat16* y = Yv + (size_t)row * DM;
    int t = threadIdx.x;
    float v[3], s = 0.f, s2 = 0.f;
#pragma unroll
    for (int i = 0; i < 3; i++) {
        int d = t + 256 * i;
        float u = __bfloat162float(x[d]) + __bfloat162float(y[d]);
        v[i] = u; s += u; s2 += u * u;
    }
    __shared__ float rs[256], rs2[256];
    rs[t] = s; rs2[t] = s2; __syncthreads();
    for (int st = 128; st > 0; st >>= 1) {
        if (t < st) { rs[t] += rs[t + st]; rs2[t] += rs2[t + st]; }
        __syncthreads();
    }
    float mean = rs[0] * (1.f / (float)DM);
    float var = rs2[0] * (1.f / (float)DM) - mean * mean;
    float inv = rsqrtf(var + 1e-5f);
#pragma unroll
    for (int i = 0; i < 3; i++) {
        int d = t + 256 * i;
        x[d] = __float2bfloat16((v[i] - mean) * inv * g[d] + b[d]);
    }
}

// ---------------- anomaly ----------------
__global__ void anomaly_kernel() {
    int n = blockIdx.x;
    if (n >= g_Ntot) return;
    int t = threadIdx.x;
    float acc = 0.f;
#pragma unroll
    for (int i = 0; i < 3; i++) {
        int d = t + 256 * i;
        float m = 0.f;
        for (int l = 0; l < LL; l++)
            m += __bfloat162float(g_Xbf[((size_t)n * LL + l) * DM + d]);
        m *= (1.f / (float)LL);
        float diff = m - g_meanE[n * DM + d];
        acc += diff * diff;
    }
    __shared__ float red[256];
    red[t] = acc; __syncthreads();
    for (int s = 128; s > 0; s >>= 1) { if (t < s) red[t] += red[t + s]; __syncthreads(); }
    if (t == 0) g_s[n] = red[0];
}

// ---------------- selection ----------------
__global__ void select_kernel() {
    int b = threadIdx.x;
    if (b >= BB) return;
    int nr = g_nresp[b];
    int ne = g_next[b];
    bool used[TT];
    int ohf[TT];
#pragma unroll
    for (int j = 0; j < TT; j++) { used[j] = false; ohf[j] = 0; }
    ohf[0] = 1;
    g_nodefull[b * TT + 0] = 0;
    for (int i = 0; i < TT - 1; i++) {
        int node = 0;
        if (i < ne) {
            float best = INFINITY; int bj = 0;
            for (int j = 0; j < nr; j++) {
                if (!used[j] && g_s[j] < best) { best = g_s[j]; bj = j; }
            }
            used[bj] = true;
            node = bj + 1;
            ohf[node] = 1;
        }
        g_nodefull[b * TT + i + 1] = node;
    }
    for (int t = 0; t < TT; t++) g_oh[b * TT + t] = ohf[t];
}

// ---------------- output writers ----------------
__global__ void out_small_kernel(float* __restrict__ out, long long off_oh,
                                 long long off_sc, long long off_tl, int has_sc) {
    int t = blockIdx.x * blockDim.x + threadIdx.x;
    if (t < BB * TT) out[off_oh + t] = (float)g_oh[t];
    else if (t < BB * TT + BB) out[off_tl + (t - BB * TT)] = (float)(1 + g_next[t - BB * TT]);
    else if (t == BB * TT + BB && has_sc) out[off_sc] = 0.f;
}
__global__ void ext_mask_kernel(float* __restrict__ out, long long off) {
    int bt = blockIdx.x;
    out[off + (size_t)bt * LL + threadIdx.x] = (float)g_oh[bt];
}
__global__ void new_msk_kernel(const float* __restrict__ amask,
                               float* __restrict__ out, long long off) {
    int bt = blockIdx.x;
    int b = bt >> 5, t = bt & 31;
    int node = g_nodefull[bt];
    float valid = (t == 0 || (t - 1) < g_next[b]) ? 1.f : 0.f;
    out[off + (size_t)bt * LL + threadIdx.x] =
        amask[((size_t)b * TT + node) * LL + threadIdx.x] * valid;
}
__global__ void new_emb_kernel(const float* __restrict__ emb,
                               float* __restrict__ out, long long off) {
    int bt = blockIdx.x / 192;
    int r = (blockIdx.x % 192) * 256 + threadIdx.x;
    int b = bt >> 5;
    int node = g_nodefull[bt];
    out[off + (size_t)bt * (LL * DM) + r] =
        emb[((size_t)b * TT + node) * (LL * DM) + r];
}

// ---------------- host ----------------
static void run_layer(__nv_bfloat16* pW, int qkvOff, int outOff, int w1Off, int w2Off,
                      const float* qkvb, const float* outb,
                      const float* g1, const float* b1,
                      const float* c1, const float* c2,
                      const float* g2, const float* b2,
                      __nv_bfloat16* pX, __nv_bfloat16* pQKV, __nv_bfloat16* pATT,
                      __nv_bfloat16* pY, __nv_bfloat16* pHID) {
    const int GY = 248;  // ceil(NMAX*64 / 128)
    mm_kernel<0><<<dim3(18, GY), 256>>>(pX, DM, pW + qkvOff, DM, qkvb, pQKV, 3 * DM, 3 * DM, DM);
    attn_kernel<<<dim3(8, 768), 256, ATTN_SMEM>>>(pQKV, pATT);
    mm_kernel<0><<<dim3(6, GY), 256>>>(pATT, DM, pW + outOff, DM, outb, pY, DM, DM, DM);
    add_ln_kernel<<<NMAX * LL, 256>>>(pX, pY, g1, b1);
    mm_kernel<1><<<dim3(16, GY), 256>>>(pX, DM, pW + w1Off, DM, c1, pHID, FF, FF, DM);
    mm_kernel<0><<<dim3(6, GY), 256>>>(pHID, FF, pW + w2Off, FF, c2, pY, DM, DM, FF);
    add_ln_kernel<<<NMAX * LL, 256>>>(pX, pY, g2, b2);
}

extern "C" void kernel_launch(void* const* d_in, const int* in_sizes, int n_in,
                              void* d_out, int out_size) {
    const int*   tree_lens = (const int*)d_in[0];
    const float* emb       = (const float*)d_in[1];
    const float* amask     = (const float*)d_in[2];
    const float* P[28];
    for (int i = 3; i < 31; i++) P[i - 3] = (const float*)d_in[i];
    float* out = (float*)d_out;

    __nv_bfloat16 *pX, *pQKV, *pATT, *pY, *pHID, *pZ, *pW;
    cudaGetSymbolAddress((void**)&pX, g_Xbf);
    cudaGetSymbolAddress((void**)&pQKV, g_QKVbf);
    cudaGetSymbolAddress((void**)&pATT, g_ATTbf);
    cudaGetSymbolAddress((void**)&pY, g_Ybf);
    cudaGetSymbolAddress((void**)&pHID, g_HIDbf);
    cudaGetSymbolAddress((void**)&pZ, g_Zbf);
    cudaGetSymbolAddress((void**)&pW, g_Wbf);

    cudaFuncSetAttribute(attn_kernel, cudaFuncAttributeMaxDynamicSharedMemorySize, ATTN_SMEM);

    const long long NE_ELEMS = (long long)BB * TT * LL * DM;
    const long long TOT_W = 512 + 32768 + 1 + 16 + NE_ELEMS + 32768;
    int has_sc = ((long long)out_size == TOT_W - 1) ? 0 : 1;
    long long off_oh = 0;
    long long off_em = 512;
    long long off_sc = 512 + 32768;
    long long off_tl = off_sc + (has_sc ? 1 : 0);
    long long off_ne = off_tl + 16;
    long long off_nm = off_ne + NE_ELEMS;

    setup_kernel<<<1, 32>>>(tree_lens);
    gather_kernel<<<dim3(NMAX, LL), 256>>>(emb, amask);
    meanE_kernel<<<dim3(NMAX, 3), 256>>>(emb);

    conv_kernel<<<512, 256>>>(P[0],  pW + OFF_EQKV, SZ_QKV);
    conv_kernel<<<512, 256>>>(P[2],  pW + OFF_EOUT, SZ_OUT);
    conv_kernel<<<512, 256>>>(P[6],  pW + OFF_EW1,  SZ_W1);
    conv_kernel<<<512, 256>>>(P[8],  pW + OFF_EW2,  SZ_W2);
    conv_kernel<<<512, 256>>>(P[12], pW + OFF_DQKV, SZ_QKV);
    conv_kernel<<<512, 256>>>(P[14], pW + OFF_DOUT, SZ_OUT);
    conv_kernel<<<512, 256>>>(P[18], pW + OFF_DW1,  SZ_W1);
    conv_kernel<<<512, 256>>>(P[20], pW + OFF_DW2,  SZ_W2);
    conv_kernel<<<128, 256>>>(P[24], pW + OFF_PE,   SZ_PE);
    conv_pad_kernel<<<(DM * 128 + 255) / 256, 256>>>(P[26], pW + OFF_PD);

    const int LQKV = 3 * DM * DM, LOUT = DM * DM, LW1 = FF * DM, LW2 = DM * FF;
    for (int i = 0; i < 2; i++)
        run_layer(pW, OFF_EQKV + i * LQKV, OFF_EOUT + i * LOUT,
                  OFF_EW1 + i * LW1, OFF_EW2 + i * LW2,
                  P[1] + (size_t)i * 3 * DM, P[3] + (size_t)i * DM,
                  P[4] + (size_t)i * DM, P[5] + (size_t)i * DM,
                  P[7] + (size_t)i * FF, P[9] + (size_t)i * DM,
                  P[10] + (size_t)i * DM, P[11] + (size_t)i * DM,
                  pX, pQKV, pATT, pY, pHID);

    mm_kernel<2><<<dim3(1, 248), 256>>>(pX, DM, pW + OFF_PE, DM, P[25], pZ, 128, ZZ, DM);
    mm_kernel<2><<<dim3(6, 248), 256>>>(pZ, 128, pW + OFF_PD, 128, P[27], pX, DM, DM, 128);

    for (int i = 0; i < 2; i++)
        run_layer(pW, OFF_DQKV + i * LQKV, OFF_DOUT + i * LOUT,
                  OFF_DW1 + i * LW1, OFF_DW2 + i * LW2,
                  P[13] + (size_t)i * 3 * DM, P[15] + (size_t)i * DM,
                  P[16] + (size_t)i * DM, P[17] + (size_t)i * DM,
                  P[19] + (size_t)i * FF, P[21] + (size_t)i * DM,
                  P[22] + (size_t)i * DM, P[23] + (size_t)i * DM,
                  pX, pQKV, pATT, pY, pHID);

    anomaly_kernel<<<NMAX, 256>>>();
    select_kernel<<<1, 32>>>();

    out_small_kernel<<<3, 256>>>(out, off_oh, off_sc, off_tl, has_sc);
    ext_mask_kernel<<<BB * TT, LL>>>(out, off_em);
    new_msk_kernel<<<BB * TT, LL>>>(amask, out, off_nm);
    new_emb_kernel<<<BB * TT * 192, 256>>>(emb, out, off_ne);
}